// round 6
// baseline (speedup 1.0000x reference)
#include <cuda_runtime.h>
#include <stdint.h>

// N=100000 nodes, F=128 feat, R=4 relations, E=1600000 edges, L=2 layers.
#define NN 100000
#define FF 128
#define RR 4
#define EE 1600000
#define NB (NN * RR)                 // (dst,relation) bins, bin = r*NN + dst
#define NBLK ((NB + 1023) / 1024)    // 391 scan blocks

// Device-global scratch (no cudaMalloc allowed).
__device__ float g_xbuf[(size_t)NN * FF];            // layer-0 output (tf32-rounded)
__device__ float g_wtf[(size_t)(RR + 1) * FF * FF];  // tf32 W[0..3] + root, current layer
__device__ int g_hist[NB];
__device__ int g_offs[NB];
__device__ int g_cursor[NB];
__device__ int g_perm[EE];                           // src indices sorted by bin
__device__ int g_bsum[NBLK];
__device__ int g_bsumx[NBLK];

__device__ __forceinline__ float to_tf32(float v) {
    float o;
    asm("cvt.rna.tf32.f32 %0, %1;" : "=f"(o) : "f"(v));
    return o;
}

// ---------------------------------------------------------------------------
// One-time counting sort of edges by (relation, dst).
// ---------------------------------------------------------------------------
__global__ void hist_zero_kernel() {
    int stride = gridDim.x * blockDim.x;
    for (int i = blockIdx.x * blockDim.x + threadIdx.x; i < NB; i += stride)
        g_hist[i] = 0;
}

__global__ void hist_build_kernel(const int* __restrict__ ei,
                                  const int* __restrict__ et) {
    int e = blockIdx.x * blockDim.x + threadIdx.x;
    if (e >= EE) return;
    int dst = __ldg(&ei[EE + e]);
    int r = __ldg(&et[e]);
    atomicAdd(&g_hist[r * NN + dst], 1);
}

__global__ void scan1_kernel() {
    __shared__ int sh[256];
    int t = threadIdx.x;
    int base = blockIdx.x * 1024 + t * 4;
    int v0 = (base + 0 < NB) ? g_hist[base + 0] : 0;
    int v1 = (base + 1 < NB) ? g_hist[base + 1] : 0;
    int v2 = (base + 2 < NB) ? g_hist[base + 2] : 0;
    int v3 = (base + 3 < NB) ? g_hist[base + 3] : 0;
    int s = v0 + v1 + v2 + v3;
    sh[t] = s;
    __syncthreads();
    for (int off = 1; off < 256; off <<= 1) {
        int add = (t >= off) ? sh[t - off] : 0;
        __syncthreads();
        sh[t] += add;
        __syncthreads();
    }
    int excl = sh[t] - s;
    if (base + 0 < NB) g_offs[base + 0] = excl;
    excl += v0;
    if (base + 1 < NB) g_offs[base + 1] = excl;
    excl += v1;
    if (base + 2 < NB) g_offs[base + 2] = excl;
    excl += v2;
    if (base + 3 < NB) g_offs[base + 3] = excl;
    if (t == 255) g_bsum[blockIdx.x] = sh[255];
}

__global__ void scan2_kernel() {
    __shared__ int sh[512];
    int t = threadIdx.x;
    int v = (t < NBLK) ? g_bsum[t] : 0;
    sh[t] = v;
    __syncthreads();
    for (int off = 1; off < 512; off <<= 1) {
        int add = (t >= off) ? sh[t - off] : 0;
        __syncthreads();
        sh[t] += add;
        __syncthreads();
    }
    if (t < NBLK) g_bsumx[t] = sh[t] - v;
}

__global__ void scan3_kernel() {
    int add = g_bsumx[blockIdx.x];
    int base = blockIdx.x * 1024 + threadIdx.x * 4;
#pragma unroll
    for (int j = 0; j < 4; ++j) {
        int i = base + j;
        if (i < NB) {
            int o = g_offs[i] + add;
            g_offs[i] = o;
            g_cursor[i] = o;
        }
    }
}

__global__ void place_kernel(const int* __restrict__ ei,
                             const int* __restrict__ et) {
    int e = blockIdx.x * blockDim.x + threadIdx.x;
    if (e >= EE) return;
    int src = __ldg(&ei[e]);
    int dst = __ldg(&ei[EE + e]);
    int r = __ldg(&et[e]);
    int pos = atomicAdd(&g_cursor[r * NN + dst], 1);
    g_perm[pos] = src;
}

// ---------------------------------------------------------------------------
// Pre-round this layer's weights (W[4] then root) into g_wtf. 20480 float4.
// ---------------------------------------------------------------------------
__global__ void convert_w_kernel(const float* __restrict__ W,
                                 const float* __restrict__ root) {
    int i = blockIdx.x * blockDim.x + threadIdx.x;   // 0..20479
    const int wquads = RR * FF * FF / 4;             // 16384
    float4 v;
    if (i < wquads) v = reinterpret_cast<const float4*>(W)[i];
    else            v = reinterpret_cast<const float4*>(root)[i - wquads];
    v.x = to_tf32(v.x); v.y = to_tf32(v.y);
    v.z = to_tf32(v.z); v.w = to_tf32(v.w);
    reinterpret_cast<float4*>(g_wtf)[i] = v;
}

// ---------------------------------------------------------------------------
// FUSED layer kernel: gather-mean aggregation + tf32 mma GEMM + bias + relu.
//   out[n,:] = relu( sum_r mean_r[n,:]@W_r + x[n,:]@root + bias )
// Block = 128 dst rows x 128 output cols; K = 5 segments of 128.
// Per segment: 8 warps build the 128x128 A-tile in smem (16 bins/warp,
// segmented gather over sorted edges, mean + tf32-round at STS), then
// 8 BK=16 chunks of m16n8k8 tf32 mma with double-buffered cp.async B.
// 256 threads = 8 warps in 2(M)x4(N); warp tile 64x32.
// ---------------------------------------------------------------------------
#define A_LDF 132
#define A_FLOATS (128 * A_LDF)          // 16896 floats
#define B_LDF 132
#define B_CHUNKF (16 * B_LDF)           // 2112 floats per buffer
#define FUSED_SMEM ((A_FLOATS + 2 * B_CHUNKF) * 4)  // 84480 bytes

__device__ __forceinline__ void issueB(int seg, int kc, int buf, uint32_t sB) {
    const int tid = threadIdx.x;
    const float* Bseg = g_wtf + (size_t)seg * FF * FF;
#pragma unroll
    for (int t = 0; t < 2; ++t) {
        int idx = tid + t * 256;        // 0..511
        int k = idx >> 5;               // 0..15
        int c16 = idx & 31;             // 0..31
        const float* src = Bseg + (size_t)(kc * 16 + k) * FF + c16 * 4;
        uint32_t dst = sB + (buf * B_CHUNKF + k * B_LDF + c16 * 4) * 4;
        asm volatile("cp.async.cg.shared.global [%0], [%1], 16;\n"
                     :: "r"(dst), "l"(src));
    }
}

__global__ __launch_bounds__(256, 2)
void fused_kernel(const float* __restrict__ xext,  // gather+root input (layer 0)
                  int xsel,                        // 0 -> xext, 1 -> g_xbuf
                  const float* __restrict__ bias,
                  float* __restrict__ outp,        // nullptr -> g_xbuf
                  int round_out) {
    const float* __restrict__ x = xsel ? g_xbuf : xext;
    float* __restrict__ xout = outp ? outp : g_xbuf;
    const float4* __restrict__ x4 = reinterpret_cast<const float4*>(x);

    extern __shared__ float smem[];
    float* As = smem;                        // [128][A_LDF]
    uint32_t sB = (uint32_t)__cvta_generic_to_shared(smem + A_FLOATS);
    const float* Bsm = smem + A_FLOATS;      // [2][16][B_LDF]

    const int tid = threadIdx.x;
    const int lane = tid & 31;
    const int wid = tid >> 5;        // 0..7
    const int warp_m = wid & 1;      // rows warp_m*64
    const int warp_n = wid >> 1;     // cols warp_n*32
    const int q = lane >> 2;         // 0..7
    const int c = lane & 3;          // 0..3
    const int row0 = blockIdx.x * 128;

    float acc[4][4][4];
#pragma unroll
    for (int mi = 0; mi < 4; ++mi)
#pragma unroll
        for (int ni = 0; ni < 4; ++ni)
#pragma unroll
            for (int j = 0; j < 4; ++j) acc[mi][ni][j] = 0.f;

    for (int seg = 0; seg < 5; ++seg) {
        // Kick off the first B chunk; it lands during the gather phase.
        issueB(seg, 0, 0, sB);
        asm volatile("cp.async.commit_group;\n" ::: "memory");

        // ---- Build A tile (128 x 128) in smem ----
        if (seg < RR) {
#pragma unroll 1
            for (int rr = 0; rr < 16; ++rr) {
                int row = wid * 16 + rr;
                int gr = row0 + row;
                int start = 0, cnt = 0;
                if (gr < NN) {
                    int b = seg * NN + gr;
                    start = __ldg(&g_offs[b]);
                    cnt = __ldg(&g_hist[b]);
                }
                float4 a0 = make_float4(0.f, 0.f, 0.f, 0.f);
                float4 a1 = make_float4(0.f, 0.f, 0.f, 0.f);
                int i = 0;
                for (; i + 1 < cnt; i += 2) {
                    int s0 = __ldg(&g_perm[start + i]);
                    int s1 = __ldg(&g_perm[start + i + 1]);
                    float4 v0 = __ldg(x4 + (size_t)s0 * 32 + lane);
                    float4 v1 = __ldg(x4 + (size_t)s1 * 32 + lane);
                    a0.x += v0.x; a0.y += v0.y; a0.z += v0.z; a0.w += v0.w;
                    a1.x += v1.x; a1.y += v1.y; a1.z += v1.z; a1.w += v1.w;
                }
                if (i < cnt) {
                    int s0 = __ldg(&g_perm[start + i]);
                    float4 v0 = __ldg(x4 + (size_t)s0 * 32 + lane);
                    a0.x += v0.x; a0.y += v0.y; a0.z += v0.z; a0.w += v0.w;
                }
                float inv = (cnt > 0) ? 1.0f / (float)cnt : 0.f;
                float4 m;
                m.x = to_tf32((a0.x + a1.x) * inv);
                m.y = to_tf32((a0.y + a1.y) * inv);
                m.z = to_tf32((a0.z + a1.z) * inv);
                m.w = to_tf32((a0.w + a1.w) * inv);
                *reinterpret_cast<float4*>(&As[row * A_LDF + lane * 4]) = m;
            }
        } else {
            // Root segment: A = x (tf32-rounded).
#pragma unroll 1
            for (int rr = 0; rr < 16; ++rr) {
                int row = wid * 16 + rr;
                int gr = row0 + row;
                float4 v = make_float4(0.f, 0.f, 0.f, 0.f);
                if (gr < NN) v = __ldg(x4 + (size_t)gr * 32 + lane);
                v.x = to_tf32(v.x); v.y = to_tf32(v.y);
                v.z = to_tf32(v.z); v.w = to_tf32(v.w);
                *reinterpret_cast<float4*>(&As[row * A_LDF + lane * 4]) = v;
            }
        }

        // ---- 8 BK=16 mma chunks, double-buffered B ----
        for (int kc = 0; kc < 8; ++kc) {
            if (kc < 7) issueB(seg, kc + 1, (kc + 1) & 1, sB);
            asm volatile("cp.async.commit_group;\n" ::: "memory");
            if (kc < 7)
                asm volatile("cp.async.wait_group 1;\n" ::: "memory");
            else
                asm volatile("cp.async.wait_group 0;\n" ::: "memory");
            __syncthreads();   // B chunk ready + A tile built (kc==0)

            const int buf = kc & 1;
            const int kb0 = kc * 16;
#pragma unroll
            for (int ks = 0; ks < 2; ++ks) {
                const int kb = kb0 + ks * 8;       // global k in A
                const int lkb = ks * 8;            // local k in B chunk
                uint32_t a[4][4];
#pragma unroll
                for (int mi = 0; mi < 4; ++mi) {
                    int row = warp_m * 64 + mi * 16 + q;
                    a[mi][0] = __float_as_uint(As[row * A_LDF + kb + c]);
                    a[mi][1] = __float_as_uint(As[(row + 8) * A_LDF + kb + c]);
                    a[mi][2] = __float_as_uint(As[row * A_LDF + kb + c + 4]);
                    a[mi][3] = __float_as_uint(As[(row + 8) * A_LDF + kb + c + 4]);
                }
                uint32_t b[4][2];
#pragma unroll
                for (int ni = 0; ni < 4; ++ni) {
                    int col = warp_n * 32 + ni * 8 + q;
                    b[ni][0] = __float_as_uint(Bsm[buf * B_CHUNKF + (lkb + c) * B_LDF + col]);
                    b[ni][1] = __float_as_uint(Bsm[buf * B_CHUNKF + (lkb + c + 4) * B_LDF + col]);
                }
#pragma unroll
                for (int mi = 0; mi < 4; ++mi)
#pragma unroll
                    for (int ni = 0; ni < 4; ++ni) {
                        asm volatile(
                            "mma.sync.aligned.m16n8k8.row.col.f32.tf32.tf32.f32 "
                            "{%0,%1,%2,%3}, {%4,%5,%6,%7}, {%8,%9}, {%0,%1,%2,%3};\n"
                            : "+f"(acc[mi][ni][0]), "+f"(acc[mi][ni][1]),
                              "+f"(acc[mi][ni][2]), "+f"(acc[mi][ni][3])
                            : "r"(a[mi][0]), "r"(a[mi][1]), "r"(a[mi][2]), "r"(a[mi][3]),
                              "r"(b[ni][0]), "r"(b[ni][1]));
                    }
            }
            __syncthreads();   // done reading this B buffer / A before rewrite
        }
    }

    // Epilogue: bias + relu; tf32-round when feeding layer 1.
#pragma unroll
    for (int ni = 0; ni < 4; ++ni) {
        int col = warp_n * 32 + ni * 8 + c * 2;
        float b0 = __ldg(&bias[col]);
        float b1 = __ldg(&bias[col + 1]);
#pragma unroll
        for (int mi = 0; mi < 4; ++mi) {
            int gr0 = row0 + warp_m * 64 + mi * 16 + q;
            if (gr0 < NN) {
                float2 o;
                o.x = fmaxf(acc[mi][ni][0] + b0, 0.f);
                o.y = fmaxf(acc[mi][ni][1] + b1, 0.f);
                if (round_out) { o.x = to_tf32(o.x); o.y = to_tf32(o.y); }
                *reinterpret_cast<float2*>(xout + (size_t)gr0 * FF + col) = o;
            }
            int gr1 = gr0 + 8;
            if (gr1 < NN) {
                float2 o;
                o.x = fmaxf(acc[mi][ni][2] + b0, 0.f);
                o.y = fmaxf(acc[mi][ni][3] + b1, 0.f);
                if (round_out) { o.x = to_tf32(o.x); o.y = to_tf32(o.y); }
                *reinterpret_cast<float2*>(xout + (size_t)gr1 * FF + col) = o;
            }
        }
    }
}

// ---------------------------------------------------------------------------
extern "C" void kernel_launch(void* const* d_in, const int* in_sizes, int n_in,
                              void* d_out, int out_size) {
    const float* x       = (const float*)d_in[0];   // [N, F] f32
    const int*   ei      = (const int*)d_in[1];     // [2, E] int32
    const int*   et      = (const int*)d_in[2];     // [E]    int32
    const float* weights = (const float*)d_in[3];   // [L, R, F, F]
    const float* roots   = (const float*)d_in[4];   // [L, F, F]
    const float* biases  = (const float*)d_in[5];   // [L, F]
    float* out           = (float*)d_out;           // [N, F]

    const int edge_blocks  = (EE + 255) / 256;      // 6250
    const int fused_blocks = (NN + 127) / 128;      // 782

    cudaFuncSetAttribute(fused_kernel,
                         cudaFuncAttributeMaxDynamicSharedMemorySize, FUSED_SMEM);

    // One-time: counting sort of edges by (relation, dst).
    hist_zero_kernel<<<512, 256>>>();
    hist_build_kernel<<<edge_blocks, 256>>>(ei, et);
    scan1_kernel<<<NBLK, 256>>>();
    scan2_kernel<<<1, 512>>>();
    scan3_kernel<<<NBLK, 256>>>();
    place_kernel<<<edge_blocks, 256>>>(ei, et);

    // Layer 0: x -> g_xbuf
    convert_w_kernel<<<80, 256>>>(weights, roots);
    fused_kernel<<<fused_blocks, 256, FUSED_SMEM>>>(x, 0, biases, nullptr, 1);

    // Layer 1: g_xbuf -> out
    convert_w_kernel<<<80, 256>>>(weights + (size_t)RR * FF * FF,
                                  roots + (size_t)FF * FF);
    fused_kernel<<<fused_blocks, 256, FUSED_SMEM>>>(nullptr, 1, biases + FF, out, 0);
}

// round 8
// speedup vs baseline: 1.6661x; 1.6661x over previous
#include <cuda_runtime.h>
#include <cuda_fp16.h>
#include <stdint.h>

// N=100000 nodes, F=128 feat, R=4 relations, E=1600000 edges, L=2 layers.
#define NN 100000
#define FF 128
#define RR 4
#define EE 1600000
#define NB (NN * RR)                 // (dst,relation) bins, bin = r*NN + dst
#define NBLK ((NB + 1023) / 1024)    // 391 scan blocks
#define NSEG 5                       // 4 relations + root per layer

// Device-global scratch (no cudaMalloc allowed). fp16 activations/means/weights.
__device__ uint2 g_xh[(size_t)NN * 32];          // x as fp16 [N][128]
__device__ uint2 g_xh2[(size_t)NN * 32];         // layer-0 output as fp16
__device__ uint2 g_aggh[(size_t)RR * NN * 32];   // per-bin mean as fp16
__device__ __half g_wh[(size_t)2 * NSEG * FF * FF];  // [layer*5+seg][n][k] fp16 (transposed)
__device__ int g_hist[NB];
__device__ int g_offs[NB];
__device__ int g_cursor[NB];
__device__ int g_perm[EE];                       // src indices sorted by bin
__device__ int g_bsum[NBLK];
__device__ int g_bsumx[NBLK];

// Bit-cast helpers (no __half2_as_uint in the CUDA headers).
__device__ __forceinline__ uint32_t h2_to_u32(__half2 h) {
    return *reinterpret_cast<uint32_t*>(&h);
}
__device__ __forceinline__ __half2 u32_to_h2(uint32_t u) {
    return *reinterpret_cast<__half2*>(&u);
}

// ---------------------------------------------------------------------------
// One-time conversions
// ---------------------------------------------------------------------------
__global__ void convert_x_kernel(const float* __restrict__ x) {
    size_t stride = (size_t)gridDim.x * blockDim.x;
    const float4* in = reinterpret_cast<const float4*>(x);
    for (size_t i = (size_t)blockIdx.x * blockDim.x + threadIdx.x;
         i < (size_t)NN * 32; i += stride) {
        float4 v = in[i];
        uint2 o;
        o.x = h2_to_u32(__floats2half2_rn(v.x, v.y));
        o.y = h2_to_u32(__floats2half2_rn(v.z, v.w));
        g_xh[i] = o;
    }
}

// Both layers' weights+roots -> fp16, TRANSPOSED to [n][k] per segment.
__global__ void convert_w_kernel(const float* __restrict__ weights,
                                 const float* __restrict__ roots) {
    int i = blockIdx.x * blockDim.x + threadIdx.x;     // 0 .. 2*5*16384-1
    if (i >= 2 * NSEG * FF * FF) return;
    int si = i >> 14;            // global segment 0..9
    int rem = i & 16383;
    int n = rem >> 7;            // 0..127
    int k = rem & 127;
    int l = si / NSEG;
    int seg = si % NSEG;
    const float* src = (seg < RR)
        ? weights + ((size_t)(l * RR + seg)) * FF * FF
        : roots + (size_t)l * FF * FF;
    g_wh[i] = __float2half_rn(src[k * FF + n]);
}

// ---------------------------------------------------------------------------
// One-time counting sort of edges by (relation, dst).
// ---------------------------------------------------------------------------
__global__ void hist_zero_kernel() {
    int stride = gridDim.x * blockDim.x;
    for (int i = blockIdx.x * blockDim.x + threadIdx.x; i < NB; i += stride)
        g_hist[i] = 0;
}

__global__ void hist_build_kernel(const int* __restrict__ ei,
                                  const int* __restrict__ et) {
    int e = blockIdx.x * blockDim.x + threadIdx.x;
    if (e >= EE) return;
    int dst = __ldg(&ei[EE + e]);
    int r = __ldg(&et[e]);
    atomicAdd(&g_hist[r * NN + dst], 1);
}

__global__ void scan1_kernel() {
    __shared__ int sh[256];
    int t = threadIdx.x;
    int base = blockIdx.x * 1024 + t * 4;
    int v0 = (base + 0 < NB) ? g_hist[base + 0] : 0;
    int v1 = (base + 1 < NB) ? g_hist[base + 1] : 0;
    int v2 = (base + 2 < NB) ? g_hist[base + 2] : 0;
    int v3 = (base + 3 < NB) ? g_hist[base + 3] : 0;
    int s = v0 + v1 + v2 + v3;
    sh[t] = s;
    __syncthreads();
    for (int off = 1; off < 256; off <<= 1) {
        int add = (t >= off) ? sh[t - off] : 0;
        __syncthreads();
        sh[t] += add;
        __syncthreads();
    }
    int excl = sh[t] - s;
    if (base + 0 < NB) g_offs[base + 0] = excl;
    excl += v0;
    if (base + 1 < NB) g_offs[base + 1] = excl;
    excl += v1;
    if (base + 2 < NB) g_offs[base + 2] = excl;
    excl += v2;
    if (base + 3 < NB) g_offs[base + 3] = excl;
    if (t == 255) g_bsum[blockIdx.x] = sh[255];
}

__global__ void scan2_kernel() {
    __shared__ int sh[512];
    int t = threadIdx.x;
    int v = (t < NBLK) ? g_bsum[t] : 0;
    sh[t] = v;
    __syncthreads();
    for (int off = 1; off < 512; off <<= 1) {
        int add = (t >= off) ? sh[t - off] : 0;
        __syncthreads();
        sh[t] += add;
        __syncthreads();
    }
    if (t < NBLK) g_bsumx[t] = sh[t] - v;
}

__global__ void scan3_kernel() {
    int add = g_bsumx[blockIdx.x];
    int base = blockIdx.x * 1024 + threadIdx.x * 4;
#pragma unroll
    for (int j = 0; j < 4; ++j) {
        int i = base + j;
        if (i < NB) {
            int o = g_offs[i] + add;
            g_offs[i] = o;
            g_cursor[i] = o;
        }
    }
}

__global__ void place_kernel(const int* __restrict__ ei,
                             const int* __restrict__ et) {
    int e = blockIdx.x * blockDim.x + threadIdx.x;
    if (e >= EE) return;
    int src = __ldg(&ei[e]);
    int dst = __ldg(&ei[EE + e]);
    int r = __ldg(&et[e]);
    int pos = atomicAdd(&g_cursor[r * NN + dst], 1);
    g_perm[pos] = src;
}

// ---------------------------------------------------------------------------
// Segmented mean aggregation in fp16: one warp per bin, uint2 (4 halves) per
// lane. fp32 accumulation, fp16 mean written once. 256B/edge gather.
// ---------------------------------------------------------------------------
__global__ void aggregate_kernel(int xsel) {
    const uint2* __restrict__ xp = xsel ? g_xh2 : g_xh;
    int w = (int)(((size_t)blockIdx.x * blockDim.x + threadIdx.x) >> 5);
    int lane = threadIdx.x & 31;
    if (w >= NB) return;

    int start = __ldg(&g_offs[w]);
    int cnt = __ldg(&g_hist[w]);

    float2 a0 = make_float2(0.f, 0.f), a1 = make_float2(0.f, 0.f);
    float2 b0 = make_float2(0.f, 0.f), b1 = make_float2(0.f, 0.f);
    int i = 0;
    for (; i + 1 < cnt; i += 2) {
        int s0 = __ldg(&g_perm[start + i]);
        int s1 = __ldg(&g_perm[start + i + 1]);
        uint2 v0 = __ldg(xp + (size_t)s0 * 32 + lane);
        uint2 v1 = __ldg(xp + (size_t)s1 * 32 + lane);
        float2 f;
        f = __half22float2(u32_to_h2(v0.x)); a0.x += f.x; a0.y += f.y;
        f = __half22float2(u32_to_h2(v0.y)); a1.x += f.x; a1.y += f.y;
        f = __half22float2(u32_to_h2(v1.x)); b0.x += f.x; b0.y += f.y;
        f = __half22float2(u32_to_h2(v1.y)); b1.x += f.x; b1.y += f.y;
    }
    if (i < cnt) {
        int s0 = __ldg(&g_perm[start + i]);
        uint2 v0 = __ldg(xp + (size_t)s0 * 32 + lane);
        float2 f;
        f = __half22float2(u32_to_h2(v0.x)); a0.x += f.x; a0.y += f.y;
        f = __half22float2(u32_to_h2(v0.y)); a1.x += f.x; a1.y += f.y;
    }
    float inv = (cnt > 0) ? 1.0f / (float)cnt : 0.f;
    uint2 o;
    o.x = h2_to_u32(__floats2half2_rn((a0.x + b0.x) * inv, (a0.y + b0.y) * inv));
    o.y = h2_to_u32(__floats2half2_rn((a1.x + b1.x) * inv, (a1.y + b1.y) * inv));
    g_aggh[(size_t)w * 32 + lane] = o;
}

// ---------------------------------------------------------------------------
// fp16 tensor GEMM: out[n,:] = relu( sum_r mean_r[n,:]@W_r + x[n,:]@root + bias ).
// Virtual [N,640]x[640,128] fp16 mma m16n8k16, fp32 accumulate.
// BM=128, BN=128, BK=32 -> 20 chunks, 3-stage cp.async pipeline.
// 256 threads = 8 warps 2(M)x4(N), warp tile 64x32.
// Smem tiles as u32 arrays with row stride 20 (conflict-free fragment LDS).
// ---------------------------------------------------------------------------
#define T_STRIDE 20                       // u32 per row
#define T_BUF (128 * T_STRIDE)            // u32 per tile buffer
#define GEMM_SMEM (3 * 2 * T_BUF * 4)     // 3 stages x (A+B) = 61440 B

__device__ __forceinline__ void issue_chunk(int ct, int stage, int row0,
                                            const uint2* __restrict__ xroot,
                                            int wbase, uint32_t sA, uint32_t sB) {
    const int tid = threadIdx.x;
    const int seg = ct >> 2;                   // 0..4
    const int kloc = (ct & 3) << 5;            // 0,32,64,96 (halves)
    const __half* Abase = (seg < RR)
        ? reinterpret_cast<const __half*>(g_aggh) + ((size_t)seg * NN) * FF
        : reinterpret_cast<const __half*>(xroot);
    const __half* Bbase = g_wh + (size_t)(wbase + seg) * FF * FF;

    // A: 128 rows x 32 halves (64B) = 512 x 16B granules, 2/thread.
#pragma unroll
    for (int t = 0; t < 2; ++t) {
        int idx = tid + t * 256;
        int r = idx >> 2;                      // 0..127
        int g16 = idx & 3;                     // 16B granule in row
        int gr = row0 + r;
        const __half* src = Abase + (size_t)gr * FF + kloc + g16 * 8;
        uint32_t dst = sA + (stage * 2 * T_BUF + r * T_STRIDE + g16 * 4) * 4;
        int p = (gr < NN) ? 16 : 0;
        asm volatile("cp.async.cg.shared.global [%0], [%1], 16, %2;\n"
                     :: "r"(dst), "l"(src), "r"(p));
    }
    // B: 128 n-rows x 32 k-halves (64B), same shape.
#pragma unroll
    for (int t = 0; t < 2; ++t) {
        int idx = tid + t * 256;
        int n = idx >> 2;
        int g16 = idx & 3;
        const __half* src = Bbase + (size_t)n * FF + kloc + g16 * 8;
        uint32_t dst = sB + (stage * 2 * T_BUF + n * T_STRIDE + g16 * 4) * 4;
        asm volatile("cp.async.cg.shared.global [%0], [%1], 16;\n"
                     :: "r"(dst), "l"(src));
    }
}

__global__ __launch_bounds__(256, 2)
void gemm_kernel(int xroot_sel,                 // 0 -> g_xh, 1 -> g_xh2
                 int wbase,                     // 0 (layer0) or NSEG (layer1)
                 const float* __restrict__ bias,
                 float* __restrict__ out_f32,   // non-null: final fp32 output
                 int out_h_sel) {               // else: 1 -> write fp16 g_xh2
    const uint2* __restrict__ xroot = xroot_sel ? g_xh2 : g_xh;

    extern __shared__ uint32_t smem[];
    uint32_t* As = smem;                        // stage*2*T_BUF + row*T_STRIDE
    uint32_t* Bs = smem + T_BUF;
    uint32_t sA = (uint32_t)__cvta_generic_to_shared(As);
    uint32_t sB = (uint32_t)__cvta_generic_to_shared(Bs);

    const int tid = threadIdx.x;
    const int lane = tid & 31;
    const int wid = tid >> 5;
    const int warp_m = wid & 1;       // rows warp_m*64
    const int warp_n = wid >> 1;      // cols warp_n*32
    const int q = lane >> 2;
    const int c = lane & 3;
    const int row0 = blockIdx.x * 128;

    float acc[4][4][4];
#pragma unroll
    for (int mi = 0; mi < 4; ++mi)
#pragma unroll
        for (int ni = 0; ni < 4; ++ni)
#pragma unroll
            for (int j = 0; j < 4; ++j) acc[mi][ni][j] = 0.f;

    issue_chunk(0, 0, row0, xroot, wbase, sA, sB);
    asm volatile("cp.async.commit_group;\n" ::: "memory");
    issue_chunk(1, 1, row0, xroot, wbase, sA, sB);
    asm volatile("cp.async.commit_group;\n" ::: "memory");

    for (int ct = 0; ct < 20; ++ct) {
        if (ct + 2 < 20) {
            issue_chunk(ct + 2, (ct + 2) % 3, row0, xroot, wbase, sA, sB);
            asm volatile("cp.async.commit_group;\n" ::: "memory");
            asm volatile("cp.async.wait_group 2;\n" ::: "memory");
        } else if (ct + 1 < 20) {
            asm volatile("cp.async.wait_group 1;\n" ::: "memory");
        } else {
            asm volatile("cp.async.wait_group 0;\n" ::: "memory");
        }
        __syncthreads();

        const int stage = ct % 3;
        const uint32_t* Ab = As + stage * 2 * T_BUF;
        const uint32_t* Bb = Bs + stage * 2 * T_BUF;
#pragma unroll
        for (int ks = 0; ks < 2; ++ks) {        // two k16 steps per BK=32
            const int ko = ks * 8;              // u32 offset (16 halves)
            uint32_t a[4][4];
#pragma unroll
            for (int mi = 0; mi < 4; ++mi) {
                int row = warp_m * 64 + mi * 16 + q;
                a[mi][0] = Ab[row * T_STRIDE + ko + c];
                a[mi][1] = Ab[(row + 8) * T_STRIDE + ko + c];
                a[mi][2] = Ab[row * T_STRIDE + ko + c + 4];
                a[mi][3] = Ab[(row + 8) * T_STRIDE + ko + c + 4];
            }
            uint32_t b[4][2];
#pragma unroll
            for (int ni = 0; ni < 4; ++ni) {
                int col = warp_n * 32 + ni * 8 + q;
                b[ni][0] = Bb[col * T_STRIDE + ko + c];
                b[ni][1] = Bb[col * T_STRIDE + ko + c + 4];
            }
#pragma unroll
            for (int mi = 0; mi < 4; ++mi)
#pragma unroll
                for (int ni = 0; ni < 4; ++ni) {
                    asm volatile(
                        "mma.sync.aligned.m16n8k16.row.col.f32.f16.f16.f32 "
                        "{%0,%1,%2,%3}, {%4,%5,%6,%7}, {%8,%9}, {%0,%1,%2,%3};\n"
                        : "+f"(acc[mi][ni][0]), "+f"(acc[mi][ni][1]),
                          "+f"(acc[mi][ni][2]), "+f"(acc[mi][ni][3])
                        : "r"(a[mi][0]), "r"(a[mi][1]), "r"(a[mi][2]), "r"(a[mi][3]),
                          "r"(b[ni][0]), "r"(b[ni][1]));
                }
        }
        __syncthreads();
    }

    // Epilogue: bias + relu. Either fp32 (final) or fp16 (inter-layer).
#pragma unroll
    for (int ni = 0; ni < 4; ++ni) {
        int col = warp_n * 32 + ni * 8 + c * 2;
        float b0 = __ldg(&bias[col]);
        float b1 = __ldg(&bias[col + 1]);
#pragma unroll
        for (int mi = 0; mi < 4; ++mi) {
            int gr0 = row0 + warp_m * 64 + mi * 16 + q;
            int gr1 = gr0 + 8;
            float v00 = fmaxf(acc[mi][ni][0] + b0, 0.f);
            float v01 = fmaxf(acc[mi][ni][1] + b1, 0.f);
            float v10 = fmaxf(acc[mi][ni][2] + b0, 0.f);
            float v11 = fmaxf(acc[mi][ni][3] + b1, 0.f);
            if (out_f32) {
                if (gr0 < NN)
                    *reinterpret_cast<float2*>(out_f32 + (size_t)gr0 * FF + col)
                        = make_float2(v00, v01);
                if (gr1 < NN)
                    *reinterpret_cast<float2*>(out_f32 + (size_t)gr1 * FF + col)
                        = make_float2(v10, v11);
            } else if (out_h_sel) {
                uint32_t* oh = reinterpret_cast<uint32_t*>(g_xh2);
                if (gr0 < NN)
                    oh[(size_t)gr0 * 64 + (col >> 1)] =
                        h2_to_u32(__floats2half2_rn(v00, v01));
                if (gr1 < NN)
                    oh[(size_t)gr1 * 64 + (col >> 1)] =
                        h2_to_u32(__floats2half2_rn(v10, v11));
            }
        }
    }
}

// ---------------------------------------------------------------------------
extern "C" void kernel_launch(void* const* d_in, const int* in_sizes, int n_in,
                              void* d_out, int out_size) {
    const float* x       = (const float*)d_in[0];   // [N, F] f32
    const int*   ei      = (const int*)d_in[1];     // [2, E] int32
    const int*   et      = (const int*)d_in[2];     // [E]    int32
    const float* weights = (const float*)d_in[3];   // [L, R, F, F]
    const float* roots   = (const float*)d_in[4];   // [L, F, F]
    const float* biases  = (const float*)d_in[5];   // [L, F]
    float* out           = (float*)d_out;           // [N, F]

    const int edge_blocks = (EE + 255) / 256;       // 6250
    const int agg_blocks  = (NB * 32 + 255) / 256;  // 50000
    const int gemm_blocks = (NN + 127) / 128;       // 782
    const int convw_blocks = (2 * NSEG * FF * FF + 255) / 256;

    cudaFuncSetAttribute(gemm_kernel,
                         cudaFuncAttributeMaxDynamicSharedMemorySize, GEMM_SMEM);

    // One-time: fp16 conversions + counting sort of edges by (relation, dst).
    convert_x_kernel<<<1024, 256>>>(x);
    convert_w_kernel<<<convw_blocks, 256>>>(weights, roots);
    hist_zero_kernel<<<512, 256>>>();
    hist_build_kernel<<<edge_blocks, 256>>>(ei, et);
    scan1_kernel<<<NBLK, 256>>>();
    scan2_kernel<<<1, 512>>>();
    scan3_kernel<<<NBLK, 256>>>();
    place_kernel<<<edge_blocks, 256>>>(ei, et);

    // Layer 0: g_xh -> g_xh2 (fp16)
    aggregate_kernel<<<agg_blocks, 256>>>(0);
    gemm_kernel<<<gemm_blocks, 256, GEMM_SMEM>>>(0, 0, biases, nullptr, 1);

    // Layer 1: g_xh2 -> out (fp32)
    aggregate_kernel<<<agg_blocks, 256>>>(1);
    gemm_kernel<<<gemm_blocks, 256, GEMM_SMEM>>>(1, NSEG, biases + FF, out, 0);
}